// round 4
// baseline (speedup 1.0000x reference)
#include <cuda_runtime.h>

#define NT 5
#define A_FIX 128
#define PTS_PER_BLK 128   // 256 threads, 2 threads per point

__device__ __forceinline__ float fast_sqrt(float x) {
    float r; asm("sqrt.approx.f32 %0, %1;" : "=f"(r) : "f"(x)); return r;
}
__device__ __forceinline__ float fast_ex2_neg(float x) {  // exp2(-x)
    float r; asm("{\n\t.reg .f32 t;\n\tneg.f32 t, %1;\n\tex2.approx.f32 %0, t;\n\t}"
                 : "=f"(r) : "f"(x));
    return r;
}
__device__ __forceinline__ float fast_rcp(float x) {
    float r; asm("rcp.approx.f32 %0, %1;" : "=f"(r) : "f"(x)); return r;
}
__device__ __forceinline__ float fast_rsq(float x) {
    float r; asm("rsqrt.approx.f32 %0, %1;" : "=f"(r) : "f"(x)); return r;
}

__global__ __launch_bounds__(256) void gnf_kernel(
    const float* __restrict__ coords,    // [B, A, 3]
    const int*   __restrict__ atom_types,// [B, A]
    const float* __restrict__ query,     // [B, P, 3]
    float*       __restrict__ out,       // [B, P, NT, 3]
    int P)
{
    __shared__ float4 sc[A_FIX];     // coords bucket-sorted by type, pre-scaled by log2(e)
    __shared__ int cnt[NT];
    __shared__ int off[NT + 1];

    const int b   = blockIdx.y;
    const int tid = threadIdx.x;
    const float L = 1.4426950408889634f;   // log2(e)

    // ---- per-block preprocessing: bucket atoms by type ----
    if (tid < NT) cnt[tid] = 0;
    __syncthreads();

    int myT = -1, myR = 0;
    if (tid < A_FIX) {
        int t = atom_types[b * A_FIX + tid];
        if (t >= 0 && t < NT) {
            myT = t;
            myR = atomicAdd(&cnt[t], 1);
        }
    }
    __syncthreads();
    if (tid == 0) {
        int s = 0;
        #pragma unroll
        for (int t = 0; t < NT; t++) { off[t] = s; s += cnt[t]; }
        off[NT] = s;
    }
    __syncthreads();
    if (myT >= 0) {
        const float* c = coords + (b * A_FIX + tid) * 3;
        sc[off[myT] + myR] = make_float4(c[0] * L, c[1] * L, c[2] * L, 0.0f);
    }
    __syncthreads();

    // ---- main loop: 2 threads per point (h = 0/1 split over atoms) ----
    const int h = tid & 1;
    const int p_raw = blockIdx.x * PTS_PER_BLK + (tid >> 1);
    const bool valid = (p_raw < P);
    const int p = valid ? p_raw : (P - 1);   // clamp: keep all lanes alive for shuffles

    const float* q = query + ((long)b * P + p) * 3;
    const float qx = q[0] * L, qy = q[1] * L, qz = q[2] * L;

    float* o = out + ((long)b * P + p) * (NT * 3);

    const float INVL = 0.6931471805599453f;  // ln(2) = 1/log2(e)

    #pragma unroll
    for (int t = 0; t < NT; t++) {
        const int beg = off[t], end = off[t + 1];
        float sw = 0.0f, sx = 0.0f, sy = 0.0f, sz = 0.0f;

        #pragma unroll 2
        for (int a = beg + h; a < end; a += 2) {
            float4 c = sc[a];
            float dx = c.x - qx;
            float dy = c.y - qy;
            float dz = c.z - qz;
            float d2 = fmaf(dx, dx, fmaf(dy, dy, dz * dz));
            float e  = fast_ex2_neg(fast_sqrt(d2));   // exp(-true_dist)
            sw += e;
            sx = fmaf(e, dx, sx);
            sy = fmaf(e, dy, sy);
            sz = fmaf(e, dz, sz);
        }

        // reduce across the lane pair
        sw += __shfl_xor_sync(0xFFFFFFFFu, sw, 1);
        sx += __shfl_xor_sync(0xFFFFFFFFu, sx, 1);
        sy += __shfl_xor_sync(0xFFFFFFFFu, sy, 1);
        sz += __shfl_xor_sync(0xFFFFFFFFu, sz, 1);

        // lane 0 stores types 0,2,4; lane 1 stores 1,3
        if (valid && (t & 1) == h) {
            float gx = 0.0f, gy = 0.0f, gz = 0.0f;
            if (end > beg) {
                float inv = fast_rcp(sw) * INVL;      // un-scale by log2(e) here
                gx = sx * inv; gy = sy * inv; gz = sz * inv;
                float g2 = fmaf(gx, gx, fmaf(gy, gy, gz * gz));
                float f = fminf(1.0f, 0.3f * fast_rsq(fmaxf(g2, 1e-24f)));
                gx *= f; gy *= f; gz *= f;
            }
            o[t * 3 + 0] = gx;
            o[t * 3 + 1] = gy;
            o[t * 3 + 2] = gz;
        }
    }
}

extern "C" void kernel_launch(void* const* d_in, const int* in_sizes, int n_in,
                              void* d_out, int out_size)
{
    const float* coords     = (const float*)d_in[0];  // B*A*3
    const int*   atom_types = (const int*)  d_in[1];  // B*A
    const float* query      = (const float*)d_in[2];  // B*P*3

    const int A = A_FIX;
    const int B = in_sizes[1] / A;
    const int P = in_sizes[2] / (3 * B);

    dim3 grid((P + PTS_PER_BLK - 1) / PTS_PER_BLK, B);
    gnf_kernel<<<grid, 256>>>(coords, atom_types, query, (float*)d_out, P);
}